// round 1
// baseline (speedup 1.0000x reference)
#include <cuda_runtime.h>
#include <cuda_bf16.h>
#include <math.h>

// Problem constants
#define S_LEN 2048
#define DIM   2048
#define NHEAD 16
#define QL    1536
#define KVL   512
#define NOPE  128
#define ROPE_D 64
#define VH    128
#define QKD   192   // NOPE + ROPE
#define EPS   1e-6f

// ---------------- scratch (device globals; no allocation allowed) ----------
__device__ float g_qdown[S_LEN * QL];
__device__ float g_qnorm[S_LEN * QL];
__device__ float g_kv   [S_LEN * (KVL + ROPE_D)];
__device__ float g_kvnorm[S_LEN * KVL];
__device__ float g_q    [S_LEN * NHEAD * QKD];     // roped in place
__device__ float g_kvu  [S_LEN * NHEAD * (NOPE + VH)];
__device__ float g_kpe  [S_LEN * ROPE_D];
__device__ float g_attn [S_LEN * NHEAD * VH];

// ---------------- GEMM: C[M,N] = A[M,K] * B[N,K]^T  (row-major) ------------
#define GBM 128
#define GBN 128
#define GBK 8

__global__ void __launch_bounds__(256) gemm_nt_kernel(
    const float* __restrict__ A, const float* __restrict__ B,
    float* __restrict__ C, int M, int N, int K)
{
    __shared__ float As[GBK][GBM + 4];
    __shared__ float Bs[GBK][GBN + 4];

    const int tid = threadIdx.x;
    const int tx = tid & 15;       // 0..15
    const int ty = tid >> 4;       // 0..15
    const int row0 = blockIdx.y * GBM;
    const int col0 = blockIdx.x * GBN;

    const int lr = tid >> 1;             // 0..127
    const int lc = (tid & 1) * 4;        // 0 or 4

    float acc[8][8];
#pragma unroll
    for (int i = 0; i < 8; i++)
#pragma unroll
        for (int j = 0; j < 8; j++) acc[i][j] = 0.f;

    for (int k0 = 0; k0 < K; k0 += GBK) {
        float4 av = make_float4(0.f, 0.f, 0.f, 0.f);
        if (row0 + lr < M)
            av = *(const float4*)(A + (size_t)(row0 + lr) * K + k0 + lc);
        As[lc + 0][lr] = av.x; As[lc + 1][lr] = av.y;
        As[lc + 2][lr] = av.z; As[lc + 3][lr] = av.w;

        float4 bv = make_float4(0.f, 0.f, 0.f, 0.f);
        if (col0 + lr < N)
            bv = *(const float4*)(B + (size_t)(col0 + lr) * K + k0 + lc);
        Bs[lc + 0][lr] = bv.x; Bs[lc + 1][lr] = bv.y;
        Bs[lc + 2][lr] = bv.z; Bs[lc + 3][lr] = bv.w;

        __syncthreads();

#pragma unroll
        for (int k = 0; k < GBK; ++k) {
            float a[8], b[8];
            *(float4*)(a)     = *(const float4*)&As[k][ty * 8];
            *(float4*)(a + 4) = *(const float4*)&As[k][ty * 8 + 4];
            *(float4*)(b)     = *(const float4*)&Bs[k][tx * 8];
            *(float4*)(b + 4) = *(const float4*)&Bs[k][tx * 8 + 4];
#pragma unroll
            for (int i = 0; i < 8; i++)
#pragma unroll
                for (int j = 0; j < 8; j++)
                    acc[i][j] += a[i] * b[j];
        }
        __syncthreads();
    }

#pragma unroll
    for (int i = 0; i < 8; i++) {
        int r = row0 + ty * 8 + i;
        if (r >= M) continue;
#pragma unroll
        for (int j = 0; j < 8; j++) {
            int c = col0 + tx * 8 + j;
            if (c < N) C[(size_t)r * N + c] = acc[i][j];
        }
    }
}

// ---------------- RMSNorm: out = x * rsqrt(mean(x^2)+eps) * w --------------
__global__ void rms_kernel(const float* __restrict__ in, const float* __restrict__ w,
                           float* __restrict__ out, int n, int istride, int ostride)
{
    const int row = blockIdx.x;
    const float* x = in + (size_t)row * istride;

    float ss = 0.f;
    for (int i = threadIdx.x; i < n; i += blockDim.x) {
        float v = x[i];
        ss += v * v;
    }
#pragma unroll
    for (int o = 16; o; o >>= 1) ss += __shfl_xor_sync(0xffffffffu, ss, o);

    __shared__ float warpsum[8];
    __shared__ float sScale;
    const int wid = threadIdx.x >> 5;
    if ((threadIdx.x & 31) == 0) warpsum[wid] = ss;
    __syncthreads();
    if (threadIdx.x == 0) {
        float tot = 0.f;
        for (int i = 0; i < (int)(blockDim.x >> 5); i++) tot += warpsum[i];
        sScale = rsqrtf(tot / (float)n + EPS);
    }
    __syncthreads();
    const float sc = sScale;
    for (int i = threadIdx.x; i < n; i += blockDim.x)
        out[(size_t)row * ostride + i] = x[i] * sc * w[i];
}

// ---------------- RoPE: q_pe (in place on g_q) and k_pe -> g_kpe -----------
__global__ void rope_kernel(float* __restrict__ q, const float* __restrict__ kv,
                            float* __restrict__ kpe)
{
    const int s = blockIdx.x;
    const int tid = threadIdx.x;        // 544 = 17 warps
    const int h = tid >> 5;             // 0..16
    const int i = tid & 31;             // freq index 0..31
    if (h > 16) return;

    const float invf = powf(10000.f, -(float)i / 32.f);
    const float ang = (float)s * invf;
    float sn, c;
    sincosf(ang, &sn, &c);

    if (h < 16) {
        float* p = q + (size_t)s * (NHEAD * QKD) + h * QKD + NOPE + 2 * i;
        const float x0 = p[0], x1 = p[1];
        p[0] = x0 * c - x1 * sn;
        p[1] = x0 * sn + x1 * c;
    } else {
        const float* p = kv + (size_t)s * (KVL + ROPE_D) + KVL + 2 * i;
        const float x0 = p[0], x1 = p[1];
        kpe[(size_t)s * ROPE_D + 2 * i]     = x0 * c - x1 * sn;
        kpe[(size_t)s * ROPE_D + 2 * i + 1] = x0 * sn + x1 * c;
    }
}

// ---------------- Flash attention (causal, online softmax) -----------------
// grid: (S_LEN/64, NHEAD), block: 256 threads
// smem layout (floats):
//   Qt[192][68], Kt[192][68], Vs[64][132], Pt[64][68], sAlpha[64], sL[64]
#define LDT 68
#define LDV 132
#define ATTN_SMEM_FLOATS (QKD*LDT*2 + 64*LDV + 64*LDT + 128)

__global__ void __launch_bounds__(256) attn_kernel(
    const float* __restrict__ q,     // [S, H*QKD] roped
    const float* __restrict__ kvu,   // [S, H*256] (k_nope | v)
    const float* __restrict__ kpe,   // [S, 64]
    float* __restrict__ out)         // [S, H*VH]
{
    const int qt = blockIdx.x;
    const int h  = blockIdx.y;
    extern __shared__ float sm[];
    float* Qt = sm;                          // [192][68] transposed
    float* Kt = Qt + QKD * LDT;              // [192][68] transposed
    float* Vs = Kt + QKD * LDT;              // [64][132] row-major
    float* Pt = Vs + 64 * LDV;               // [64][68]  Pt[t][i]
    float* sAlpha = Pt + 64 * LDT;           // [64]
    float* sL     = sAlpha + 64;             // [64]

    const int tid = threadIdx.x;
    const int tx = tid & 15;     // 0..15
    const int ty = tid >> 4;     // 0..15

    // load Q tile transposed: Qt[d][i]
    for (int e = tid; e < 64 * (QKD / 4); e += 256) {
        int i = e / (QKD / 4), c4 = (e % (QKD / 4)) * 4;
        float4 v = *(const float4*)(q + (size_t)(qt * 64 + i) * (NHEAD * QKD) + h * QKD + c4);
        Qt[(c4 + 0) * LDT + i] = v.x; Qt[(c4 + 1) * LDT + i] = v.y;
        Qt[(c4 + 2) * LDT + i] = v.z; Qt[(c4 + 3) * LDT + i] = v.w;
    }

    float accO[4][8];
#pragma unroll
    for (int i = 0; i < 4; i++)
#pragma unroll
        for (int j = 0; j < 8; j++) accO[i][j] = 0.f;

    float m_i = -INFINITY, l_i = 0.f;      // valid for tid < 64 (row = tid)
    const float scale = rsqrtf((float)QKD);

    for (int kt = 0; kt <= qt; ++kt) {
        __syncthreads();   // protect Kt/Vs (read in previous PV) before overwrite
        // load K tile transposed: dims 0..127 from kvu, 128..191 from kpe
        for (int e = tid; e < 64 * (QKD / 4); e += 256) {
            int t = e / (QKD / 4), c4 = (e % (QKD / 4)) * 4;
            int tg = kt * 64 + t;
            float4 v;
            if (c4 < NOPE)
                v = *(const float4*)(kvu + (size_t)tg * (NHEAD * 256) + h * 256 + c4);
            else
                v = *(const float4*)(kpe + (size_t)tg * ROPE_D + (c4 - NOPE));
            Kt[(c4 + 0) * LDT + t] = v.x; Kt[(c4 + 1) * LDT + t] = v.y;
            Kt[(c4 + 2) * LDT + t] = v.z; Kt[(c4 + 3) * LDT + t] = v.w;
        }
        // load V tile row-major
        for (int e = tid; e < 64 * (VH / 4); e += 256) {
            int t = e / (VH / 4), c4 = (e % (VH / 4)) * 4;
            int tg = kt * 64 + t;
            *(float4*)&Vs[t * LDV + c4] =
                *(const float4*)(kvu + (size_t)tg * (NHEAD * 256) + h * 256 + NOPE + c4);
        }
        __syncthreads();

        // S = Q K^T : thread computes rows i=4ty+ii, cols j=4tx+jj
        float s[4][4];
#pragma unroll
        for (int a = 0; a < 4; a++)
#pragma unroll
            for (int b = 0; b < 4; b++) s[a][b] = 0.f;

        for (int d = 0; d < QKD; ++d) {
            float a[4], b[4];
            *(float4*)a = *(const float4*)&Qt[d * LDT + 4 * ty];
            *(float4*)b = *(const float4*)&Kt[d * LDT + 4 * tx];
#pragma unroll
            for (int ii = 0; ii < 4; ii++)
#pragma unroll
                for (int jj = 0; jj < 4; jj++)
                    s[ii][jj] += a[ii] * b[jj];
        }
        // write transposed into Pt[j][i]
#pragma unroll
        for (int jj = 0; jj < 4; jj++)
            *(float4*)&Pt[(4 * tx + jj) * LDT + 4 * ty] =
                make_float4(s[0][jj], s[1][jj], s[2][jj], s[3][jj]);
        __syncthreads();

        // online softmax, one thread per row
        if (tid < 64) {
            const int i = tid;
            const int tlim = (kt == qt) ? (i + 1) : 64;
            float tmax = -INFINITY;
            for (int t = 0; t < tlim; t++)
                tmax = fmaxf(tmax, Pt[t * LDT + i]);
            tmax *= scale;
            const float mn = fmaxf(m_i, tmax);
            const float alpha = (m_i == -INFINITY) ? 0.f : expf(m_i - mn);
            float lsum = 0.f;
            for (int t = 0; t < 64; t++) {
                float p = (t < tlim) ? expf(Pt[t * LDT + i] * scale - mn) : 0.f;
                Pt[t * LDT + i] = p;
                lsum += p;
            }
            l_i = l_i * alpha + lsum;
            m_i = mn;
            sAlpha[i] = alpha;
        }
        __syncthreads();

        // O = alpha*O + P @ V : rows i=4ty+ii, cols c=8tx+cc
        {
            float al[4];
#pragma unroll
            for (int ii = 0; ii < 4; ii++) al[ii] = sAlpha[4 * ty + ii];
#pragma unroll
            for (int ii = 0; ii < 4; ii++)
#pragma unroll
                for (int cc = 0; cc < 8; cc++) accO[ii][cc] *= al[ii];

            for (int t = 0; t < 64; t++) {
                float a[4], b[8];
                *(float4*)a = *(const float4*)&Pt[t * LDT + 4 * ty];
                *(float4*)(b)     = *(const float4*)&Vs[t * LDV + 8 * tx];
                *(float4*)(b + 4) = *(const float4*)&Vs[t * LDV + 8 * tx + 4];
#pragma unroll
                for (int ii = 0; ii < 4; ii++)
#pragma unroll
                    for (int cc = 0; cc < 8; cc++)
                        accO[ii][cc] += a[ii] * b[cc];
            }
        }
    }

    if (tid < 64) sL[tid] = l_i;
    __syncthreads();

#pragma unroll
    for (int ii = 0; ii < 4; ii++) {
        const int i = 4 * ty + ii;
        const float inv_l = 1.f / sL[i];
        const int row = qt * 64 + i;
#pragma unroll
        for (int cc = 0; cc < 8; cc++)
            out[(size_t)row * (NHEAD * VH) + h * VH + 8 * tx + cc] = accO[ii][cc] * inv_l;
    }
}

// ---------------- host orchestration ---------------------------------------
static inline void launch_gemm_nt(const float* A, const float* B, float* C,
                                  int M, int N, int K)
{
    dim3 grid((N + GBN - 1) / GBN, (M + GBM - 1) / GBM);
    gemm_nt_kernel<<<grid, 256>>>(A, B, C, M, N, K);
}

extern "C" void kernel_launch(void* const* d_in, const int* in_sizes, int n_in,
                              void* d_out, int out_size)
{
    const float* x        = (const float*)d_in[0];   // [S, DIM]
    const float* wq_down  = (const float*)d_in[1];   // [QL, DIM]
    const float* q_norm_w = (const float*)d_in[2];   // [QL]
    const float* wq_up    = (const float*)d_in[3];   // [H*QKD, QL]
    const float* wkv_down = (const float*)d_in[4];   // [KVL+ROPE, DIM]
    const float* kv_norm_w= (const float*)d_in[5];   // [KVL]
    const float* wkv_up   = (const float*)d_in[6];   // [H*(NOPE+VH), KVL]
    const float* wo       = (const float*)d_in[7];   // [DIM, H*VH]
    float* out = (float*)d_out;

    float *qdown, *qnorm, *kv, *kvnorm, *qbuf, *kvu, *kpe, *attn;
    cudaGetSymbolAddress((void**)&qdown,  g_qdown);
    cudaGetSymbolAddress((void**)&qnorm,  g_qnorm);
    cudaGetSymbolAddress((void**)&kv,     g_kv);
    cudaGetSymbolAddress((void**)&kvnorm, g_kvnorm);
    cudaGetSymbolAddress((void**)&qbuf,   g_q);
    cudaGetSymbolAddress((void**)&kvu,    g_kvu);
    cudaGetSymbolAddress((void**)&kpe,    g_kpe);
    cudaGetSymbolAddress((void**)&attn,   g_attn);

    // 1) q_down = x @ wq_down^T, kv = x @ wkv_down^T
    launch_gemm_nt(x, wq_down, qdown, S_LEN, QL, DIM);
    launch_gemm_nt(x, wkv_down, kv, S_LEN, KVL + ROPE_D, DIM);

    // 2) RMSNorms
    rms_kernel<<<S_LEN, 256>>>(qdown, q_norm_w, qnorm, QL, QL, QL);
    rms_kernel<<<S_LEN, 256>>>(kv, kv_norm_w, kvnorm, KVL, KVL + ROPE_D, KVL);

    // 3) up-projections
    launch_gemm_nt(qnorm, wq_up, qbuf, S_LEN, NHEAD * QKD, QL);
    launch_gemm_nt(kvnorm, wkv_up, kvu, S_LEN, NHEAD * (NOPE + VH), KVL);

    // 4) rope (q in place, k_pe to g_kpe)
    rope_kernel<<<S_LEN, 544>>>(qbuf, kv, kpe);

    // 5) causal flash attention
    size_t attn_smem = (size_t)ATTN_SMEM_FLOATS * sizeof(float);
    cudaFuncSetAttribute(attn_kernel, cudaFuncAttributeMaxDynamicSharedMemorySize,
                         (int)attn_smem);
    dim3 agrid(S_LEN / 64, NHEAD);
    attn_kernel<<<agrid, 256, attn_smem>>>(qbuf, kvu, kpe, attn);

    // 6) output projection
    launch_gemm_nt(attn, wo, out, S_LEN, DIM, DIM);
}